// round 12
// baseline (speedup 1.0000x reference)
#include <cuda_runtime.h>
#include <cstdint>

#define NN 8192
#define CONV_BLOCKS 128
#define NODES_PER_CB (NN / CONV_BLOCKS)   // 64

// Scratch + progress counters (allocation-free rule: __device__ globals).
// Zero-initialized; reset to zero by the last retiring block of kernel A
// every launch -> deterministic across graph replays.
__device__ float g_conv[NN];
__device__ float g_h[NN];
__device__ int g_c1;    // conv sub-blocks finished (0..128)
__device__ int g_ret;   // kernel-A blocks retired  (0..8192), last resets

__device__ __forceinline__ void cp_async16(uint32_t smem_addr, const void* gptr) {
    asm volatile("cp.async.cg.shared.global [%0], [%1], 16;\n"
                 :: "r"(smem_addr), "l"(gptr));
}
__device__ __forceinline__ void cp_commit() {
    asm volatile("cp.async.commit_group;\n");
}
template <int N>
__device__ __forceinline__ void cp_wait() {
    asm volatile("cp.async.wait_group %0;\n" :: "n"(N));
}

// Kernel A: conv+sigmoid fused with layer-1 matvec.
// CRITICAL ORDERING: the 128 conv-producer blocks run the conv BEFORE
// issuing their cp.asyncs, so the conv's global loads sit at the FRONT of
// the per-SM L1tex queue instead of behind ~6 CTAs x 2048 queued LDGSTS.
// The whole wave-1 grid spins on the slowest producer, so producer latency
// is the launch's critical path.
__global__ void __launch_bounds__(256) layer1_kernel(
    const float* __restrict__ nf,
    const float* __restrict__ cw,
    const float* __restrict__ cb,
    const float* __restrict__ W1,
    const float* __restrict__ b1) {
    __shared__ float4 buf[NN / 4];  // 32 KB
    __shared__ float red[8];

    const int row = blockIdx.x;
    const int tid = threadIdx.x;
    const float4* __restrict__ W4 =
        reinterpret_cast<const float4*>(W1 + (size_t)row * NN);
    const uint32_t sbase = (uint32_t)__cvta_generic_to_shared(buf);

    if (row < CONV_BLOCKS) {
        // ---- Conv FIRST (loads at queue front) ----
        if (tid < NODES_PER_CB) {
            const int i = row * NODES_PER_CB + tid;
            const float4* nrow = reinterpret_cast<const float4*>(nf + (size_t)i * 16);
            float4 w0 = reinterpret_cast<const float4*>(cw)[0];
            float4 w1 = reinterpret_cast<const float4*>(cw)[1];
            float4 w2 = reinterpret_cast<const float4*>(cw)[2];
            float4 w3 = reinterpret_cast<const float4*>(cw)[3];
            float4 a0 = nrow[0], a1 = nrow[1], a2 = nrow[2], a3 = nrow[3];
            float s = a0.x*w0.x + a0.y*w0.y + a0.z*w0.z + a0.w*w0.w
                    + a1.x*w1.x + a1.y*w1.y + a1.z*w1.z + a1.w*w1.w
                    + a2.x*w2.x + a2.y*w2.y + a2.z*w2.z + a2.w*w2.w
                    + a3.x*w3.x + a3.y*w3.y + a3.z*w3.z + a3.w*w3.w;
            s += cb[0];
            g_conv[i] = 1.0f / (1.0f + __expf(-s));
        }
        __syncthreads();
        if (tid == 0) {
            __threadfence();
            atomicAdd(&g_c1, 1);
        }
    }

    // Queue the full 32KB W row copy (zero register cost; hides the spin).
    #pragma unroll
    for (int j = 0; j < 4; ++j) {
        int i = tid + 256 * j;
        cp_async16(sbase + i * 16, W4 + i);
    }
    cp_commit();
    #pragma unroll
    for (int j = 4; j < 8; ++j) {
        int i = tid + 256 * j;
        cp_async16(sbase + i * 16, W4 + i);
    }
    cp_commit();

    // Acquire: wait for the full conv vector.
    if (tid == 0) {
        while (*(volatile int*)&g_c1 < CONV_BLOCKS) __nanosleep(32);
        __threadfence();
    }
    __syncthreads();

    const float4* __restrict__ x4 = reinterpret_cast<const float4*>(g_conv);

    float s = 0.0f;
    cp_wait<1>();
    #pragma unroll
    for (int j = 0; j < 4; ++j) {
        int i = tid + 256 * j;
        float4 a = buf[i];
        float4 v = x4[i];   // plain load: L1 flushed at launch; first touch is
                            // post-acquire -> coherent, then L1-resident.
        s += a.x * v.x + a.y * v.y + a.z * v.z + a.w * v.w;
    }
    cp_wait<0>();
    #pragma unroll
    for (int j = 4; j < 8; ++j) {
        int i = tid + 256 * j;
        float4 a = buf[i];
        float4 v = x4[i];
        s += a.x * v.x + a.y * v.y + a.z * v.z + a.w * v.w;
    }

    #pragma unroll
    for (int o = 16; o > 0; o >>= 1) s += __shfl_xor_sync(0xffffffffu, s, o);
    if ((tid & 31) == 0) red[tid >> 5] = s;
    __syncthreads();
    if (tid == 0) {
        float t = 0.0f;
        #pragma unroll
        for (int w = 0; w < 8; ++w) t += red[w];
        g_h[row] = tanhf(t + b1[row]);
        // Counter reset for graph-replay determinism.
        int prev = atomicAdd(&g_ret, 1);
        if (prev == NN - 1) {
            g_c1 = 0;
            __threadfence();
            g_ret = 0;
        }
    }
}

// Kernel B: layer-2 matvec (proven R6 kernel, unchanged).
__global__ void __launch_bounds__(256) layer2_kernel(
    const float* __restrict__ W,
    const float* __restrict__ b,
    const float* __restrict__ x,
    float* __restrict__ y) {
    __shared__ float4 buf[NN / 4];
    __shared__ float red[8];

    const int row = blockIdx.x;
    const int tid = threadIdx.x;
    const float4* __restrict__ W4 = reinterpret_cast<const float4*>(W + (size_t)row * NN);
    const float4* __restrict__ x4 = reinterpret_cast<const float4*>(x);
    const uint32_t sbase = (uint32_t)__cvta_generic_to_shared(buf);

    #pragma unroll
    for (int j = 0; j < 4; ++j) {
        int i = tid + 256 * j;
        cp_async16(sbase + i * 16, W4 + i);
    }
    cp_commit();
    #pragma unroll
    for (int j = 4; j < 8; ++j) {
        int i = tid + 256 * j;
        cp_async16(sbase + i * 16, W4 + i);
    }
    cp_commit();

    float s = 0.0f;
    cp_wait<1>();
    #pragma unroll
    for (int j = 0; j < 4; ++j) {
        int i = tid + 256 * j;
        float4 a = buf[i];
        float4 v = x4[i];
        s += a.x * v.x + a.y * v.y + a.z * v.z + a.w * v.w;
    }
    cp_wait<0>();
    #pragma unroll
    for (int j = 4; j < 8; ++j) {
        int i = tid + 256 * j;
        float4 a = buf[i];
        float4 v = x4[i];
        s += a.x * v.x + a.y * v.y + a.z * v.z + a.w * v.w;
    }

    #pragma unroll
    for (int o = 16; o > 0; o >>= 1) s += __shfl_xor_sync(0xffffffffu, s, o);
    if ((tid & 31) == 0) red[tid >> 5] = s;
    __syncthreads();
    if (tid < 8) {
        s = red[tid];
        #pragma unroll
        for (int o = 4; o > 0; o >>= 1) s += __shfl_xor_sync(0x000000ffu, s, o);
        if (tid == 0) y[row] = s + b[row];
    }
}

extern "C" void kernel_launch(void* const* d_in, const int* in_sizes, int n_in,
                              void* d_out, int out_size) {
    const float* node_features = (const float*)d_in[0]; // (8192, 16)
    const float* conv_w        = (const float*)d_in[1]; // (16,)
    const float* conv_b        = (const float*)d_in[2]; // scalar
    const float* W1            = (const float*)d_in[3]; // (8192, 8192)
    const float* b1            = (const float*)d_in[4]; // (8192,)
    const float* W2            = (const float*)d_in[5]; // (8192, 8192)
    const float* b2            = (const float*)d_in[6]; // (8192,)
    float* out = (float*)d_out;

    float* h;
    cudaGetSymbolAddress((void**)&h, g_h);

    layer1_kernel<<<NN, 256>>>(node_features, conv_w, conv_b, W1, b1);
    layer2_kernel<<<NN, 256>>>(W2, b2, h, out);
}

// round 14
// speedup vs baseline: 1.1359x; 1.1359x over previous
#include <cuda_runtime.h>
#include <cstdint>

#define NN 8192

// Scratch (allocation-free rule: __device__ globals)
__device__ float g_conv[NN];
__device__ float g_h[NN];

__device__ __forceinline__ void cp_async16(uint32_t smem_addr, const void* gptr) {
    asm volatile("cp.async.cg.shared.global [%0], [%1], 16;\n"
                 :: "r"(smem_addr), "l"(gptr));
}
__device__ __forceinline__ void cp_commit() {
    asm volatile("cp.async.commit_group;\n");
}
template <int N>
__device__ __forceinline__ void cp_wait() {
    asm volatile("cp.async.wait_group %0;\n" :: "n"(N));
}

// Kernel 1: per-node 16-wide dot + bias + sigmoid (launch-floor bound)
__global__ void __launch_bounds__(64) conv_sigmoid_kernel(
    const float* __restrict__ nf,
    const float* __restrict__ cw,
    const float* __restrict__ cb) {
    int i = blockIdx.x * 64 + threadIdx.x;
    if (i >= NN) return;
    const float4* row = reinterpret_cast<const float4*>(nf + (size_t)i * 16);
    float4 w0 = reinterpret_cast<const float4*>(cw)[0];
    float4 w1 = reinterpret_cast<const float4*>(cw)[1];
    float4 w2 = reinterpret_cast<const float4*>(cw)[2];
    float4 w3 = reinterpret_cast<const float4*>(cw)[3];
    float4 a0 = row[0], a1 = row[1], a2 = row[2], a3 = row[3];
    float s = a0.x*w0.x + a0.y*w0.y + a0.z*w0.z + a0.w*w0.w
            + a1.x*w1.x + a1.y*w1.y + a1.z*w1.z + a1.w*w1.w
            + a2.x*w2.x + a2.y*w2.y + a2.z*w2.z + a2.w*w2.w
            + a3.x*w3.x + a3.y*w3.y + a3.z*w3.z + a3.w*w3.w;
    s += cb[0];
    g_conv[i] = 1.0f / (1.0f + __expf(-s));
}

// Matvec: one row per 256-thread block, full 32KB W row via cp.async.
// __launch_bounds__(256,6) caps regs at 42 -> 6 CTAs/SM (was 4, reg-limited
// at 54 regs). Reduction scratch aliases buf (all per-thread buf reads are
// complete before the aliased write, guarded by __syncthreads) -> smem is
// exactly 32KB, keeping the smem limit at 6-7 CTAs too.
template <int APPLY_TANH>
__global__ void __launch_bounds__(256, 6) matvec_kernel(
    const float* __restrict__ W,
    const float* __restrict__ b,
    const float* __restrict__ x,
    float* __restrict__ y) {
    __shared__ float4 buf[NN / 4];  // 32768 bytes exactly

    const int row = blockIdx.x;
    const int tid = threadIdx.x;
    const float4* __restrict__ W4 = reinterpret_cast<const float4*>(W + (size_t)row * NN);
    const float4* __restrict__ x4 = reinterpret_cast<const float4*>(x);
    const uint32_t sbase = (uint32_t)__cvta_generic_to_shared(buf);

    #pragma unroll
    for (int j = 0; j < 4; ++j) {
        int i = tid + 256 * j;
        cp_async16(sbase + i * 16, W4 + i);
    }
    cp_commit();
    #pragma unroll
    for (int j = 4; j < 8; ++j) {
        int i = tid + 256 * j;
        cp_async16(sbase + i * 16, W4 + i);
    }
    cp_commit();

    float s = 0.0f;
    cp_wait<1>();
    #pragma unroll
    for (int j = 0; j < 4; ++j) {
        int i = tid + 256 * j;
        float4 a = buf[i];
        float4 v = x4[i];
        s += a.x * v.x + a.y * v.y + a.z * v.z + a.w * v.w;
    }
    cp_wait<0>();
    #pragma unroll
    for (int j = 4; j < 8; ++j) {
        int i = tid + 256 * j;
        float4 a = buf[i];
        float4 v = x4[i];
        s += a.x * v.x + a.y * v.y + a.z * v.z + a.w * v.w;
    }

    // Warp reduction
    #pragma unroll
    for (int o = 16; o > 0; o >>= 1) s += __shfl_xor_sync(0xffffffffu, s, o);

    // Cross-warp reduction, scratch aliased into buf (reads all done).
    float* red = reinterpret_cast<float*>(buf);
    __syncthreads();                 // all buf reads complete
    if ((tid & 31) == 0) red[tid >> 5] = s;
    __syncthreads();
    if (tid == 0) {
        float t = 0.0f;
        #pragma unroll
        for (int w = 0; w < 8; ++w) t += red[w];
        t += b[row];
        y[row] = APPLY_TANH ? tanhf(t) : t;
    }
}

extern "C" void kernel_launch(void* const* d_in, const int* in_sizes, int n_in,
                              void* d_out, int out_size) {
    const float* node_features = (const float*)d_in[0]; // (8192, 16)
    const float* conv_w        = (const float*)d_in[1]; // (16,)
    const float* conv_b        = (const float*)d_in[2]; // scalar
    const float* W1            = (const float*)d_in[3]; // (8192, 8192)
    const float* b1            = (const float*)d_in[4]; // (8192,)
    const float* W2            = (const float*)d_in[5]; // (8192, 8192)
    const float* b2            = (const float*)d_in[6]; // (8192,)
    float* out = (float*)d_out;

    float* conv_feats;
    float* h;
    cudaGetSymbolAddress((void**)&conv_feats, g_conv);
    cudaGetSymbolAddress((void**)&h, g_h);

    conv_sigmoid_kernel<<<NN / 64, 64>>>(node_features, conv_w, conv_b);
    matvec_kernel<1><<<NN, 256>>>(W1, b1, conv_feats, h);
    matvec_kernel<0><<<NN, 256>>>(W2, b2, h, out);
}